// round 2
// baseline (speedup 1.0000x reference)
#include <cuda_runtime.h>
#include <cuda_bf16.h>
#include <cstdint>
#include <cstddef>

// Problem constants
#define V_NODES   25000
#define E_EDGES   100000
#define NODE_IN   74
#define EDGE_IN   12
#define OUT_DIM   64
#define EHID      128
#define NSTEPS    6
#define N_EW      4096        // OUT*OUT

// ---------------------------------------------------------------------------
// Scratch (static __device__ globals -- the sanctioned way to get scratch)
// ---------------------------------------------------------------------------
__device__ float g_h  [V_NODES * OUT_DIM];              // 6.4 MB  current node feats
__device__ float g_agg[V_NODES * OUT_DIM];              // 6.4 MB  scatter accumulator
__device__ float g_z  [E_EDGES * EHID];                 // 51.2 MB edge hidden
__device__ float g_ew [(size_t)E_EDGES * N_EW];         // 1.638 GB per-edge 64x64 mats

// ---------------------------------------------------------------------------
// fma.rn.f32x2 : packed dual-FMA (ptxas never emits this from C++; 2x FFMA rate)
// ---------------------------------------------------------------------------
__device__ __forceinline__ void fma2(float2 &d, const float2 &a, const float2 &b) {
    asm("fma.rn.f32x2 %0, %1, %2, %0;"
        : "+l"(reinterpret_cast<unsigned long long &>(d))
        : "l"(reinterpret_cast<const unsigned long long &>(a)),
          "l"(reinterpret_cast<const unsigned long long &>(b)));
}

// ---------------------------------------------------------------------------
// Kernel 1: h = relu(node_feats @ Wp + bp)      [25000 x 74] @ [74 x 64]
// ---------------------------------------------------------------------------
__global__ void k_project(const float* __restrict__ nf,
                          const float* __restrict__ Wp,
                          const float* __restrict__ bp) {
    int v = blockIdx.x;
    int o = threadIdx.x;                 // 64 threads
    __shared__ float s[NODE_IN];
    for (int i = o; i < NODE_IN; i += OUT_DIM) s[i] = nf[v * NODE_IN + i];
    __syncthreads();
    float acc = bp[o];
    #pragma unroll
    for (int i = 0; i < NODE_IN; i++) acc = fmaf(s[i], Wp[i * OUT_DIM + o], acc);
    g_h[v * OUT_DIM + o] = fmaxf(acc, 0.0f);
}

// ---------------------------------------------------------------------------
// Kernel 2: z = relu(edge_feats @ We1 + be1)    [100000 x 12] @ [12 x 128]
// ---------------------------------------------------------------------------
__global__ void k_edge1(const float* __restrict__ ef,
                        const float* __restrict__ We1,
                        const float* __restrict__ be1) {
    int e = blockIdx.x;
    int k = threadIdx.x;                 // 128 threads
    __shared__ float s[EDGE_IN];
    if (k < EDGE_IN) s[k] = ef[e * EDGE_IN + k];
    __syncthreads();
    float acc = be1[k];
    #pragma unroll
    for (int j = 0; j < EDGE_IN; j++) acc = fmaf(s[j], We1[j * EHID + k], acc);
    g_z[e * EHID + k] = fmaxf(acc, 0.0f);
}

// ---------------------------------------------------------------------------
// Kernel 3: ew = z @ We2 + be2     M=100000, K=128, N=4096   (105 GFLOP)
// 128x128 tile, BK=32, 256 threads, 8x8 microtile via f32x2 FMAs, 2 CTAs/SM.
// ---------------------------------------------------------------------------
__global__ void __launch_bounds__(256, 2)
k_gemm(const float* __restrict__ W,       // We2 [128 x 4096]
       const float* __restrict__ be2) {
    __shared__ float Zs[128][36];         // [m][k] +pad (rows differ by 4 banks)
    __shared__ float Ws[32][128];         // [k][n]

    const float* Z = g_z;
    float*       C = g_ew;

    int tid = threadIdx.x;
    int tx  = tid & 15, ty = tid >> 4;
    int tx4 = tx * 4,  ty4 = ty * 4;
    int m0  = blockIdx.y * 128;
    int n0  = blockIdx.x * 128;

    float2 acc[8][4];
    #pragma unroll
    for (int r = 0; r < 8; r++)
        #pragma unroll
        for (int j = 0; j < 4; j++) acc[r][j] = make_float2(0.f, 0.f);

    for (int kc = 0; kc < EHID; kc += 32) {
        // --- load Z tile: 128 rows x 32 cols (float4 along k, coalesced) ---
        #pragma unroll
        for (int j = 0; j < 4; j++) {
            int f  = tid + 256 * j;       // 0..1023 float4 slots
            int m  = f >> 3;
            int k4 = (f & 7) * 4;
            float4 v = make_float4(0.f, 0.f, 0.f, 0.f);
            int gm = m0 + m;
            if (gm < E_EDGES)
                v = *reinterpret_cast<const float4*>(&Z[(size_t)gm * EHID + kc + k4]);
            *reinterpret_cast<float4*>(&Zs[m][k4]) = v;
        }
        // --- load W tile: 32 rows x 128 cols ---
        #pragma unroll
        for (int j = 0; j < 4; j++) {
            int f  = tid + 256 * j;       // 0..1023 float4 slots
            int kr = f >> 5;
            int c4 = (f & 31) * 4;
            *reinterpret_cast<float4*>(&Ws[kr][c4]) =
                *reinterpret_cast<const float4*>(&W[(size_t)(kc + kr) * N_EW + n0 + c4]);
        }
        __syncthreads();

        #pragma unroll
        for (int k = 0; k < 32; k++) {
            float4 b0 = *reinterpret_cast<const float4*>(&Ws[k][tx4]);
            float4 b1 = *reinterpret_cast<const float4*>(&Ws[k][64 + tx4]);
            float2 bb[4] = { make_float2(b0.x, b0.y), make_float2(b0.z, b0.w),
                             make_float2(b1.x, b1.y), make_float2(b1.z, b1.w) };
            float a[8];
            #pragma unroll
            for (int i = 0; i < 4; i++) {
                a[i]     = Zs[ty4 + i][k];
                a[4 + i] = Zs[64 + ty4 + i][k];
            }
            #pragma unroll
            for (int r = 0; r < 8; r++) {
                float2 av = make_float2(a[r], a[r]);
                #pragma unroll
                for (int j = 0; j < 4; j++) fma2(acc[r][j], av, bb[j]);
            }
        }
        __syncthreads();
    }

    // --- epilogue: +bias, guarded store ---
    float4 bia0 = *reinterpret_cast<const float4*>(&be2[n0 + tx4]);
    float4 bia1 = *reinterpret_cast<const float4*>(&be2[n0 + 64 + tx4]);
    #pragma unroll
    for (int r = 0; r < 8; r++) {
        int m = m0 + (r < 4 ? ty4 + r : 64 + ty4 + (r - 4));
        if (m < E_EDGES) {
            size_t base = (size_t)m * N_EW + n0;
            float4 o0 = make_float4(acc[r][0].x + bia0.x, acc[r][0].y + bia0.y,
                                    acc[r][1].x + bia0.z, acc[r][1].y + bia0.w);
            float4 o1 = make_float4(acc[r][2].x + bia1.x, acc[r][2].y + bia1.y,
                                    acc[r][3].x + bia1.z, acc[r][3].y + bia1.w);
            *reinterpret_cast<float4*>(&C[base + tx4])      = o0;
            *reinterpret_cast<float4*>(&C[base + 64 + tx4]) = o1;
        }
    }
}

// ---------------------------------------------------------------------------
// Kernel 4: zero the aggregation buffer
// ---------------------------------------------------------------------------
__global__ void k_zero() {
    int i = blockIdx.x * 256 + threadIdx.x;
    if (i < V_NODES * OUT_DIM) g_agg[i] = 0.0f;
}

// ---------------------------------------------------------------------------
// Kernel 5: msg[e] = h[src[e]] @ ew[e];  atomic scatter-add into agg[dst[e]]
// 4 edges per 256-thread block; streams 1.64 GB of ew -> HBM-bound.
// ---------------------------------------------------------------------------
__global__ void __launch_bounds__(256)
k_msg(const int* __restrict__ src, const int* __restrict__ dst) {
    int g = threadIdx.x >> 6;                 // edge slot in block (0..3)
    int o = threadIdx.x & 63;                 // output column
    int e = blockIdx.x * 4 + g;
    __shared__ float hs[4][OUT_DIM];

    int s = src[e];
    hs[g][o] = g_h[s * OUT_DIM + o];
    __syncthreads();

    const float* w = g_ew + (size_t)e * N_EW + o;
    float acc = 0.0f;
    #pragma unroll
    for (int i = 0; i < OUT_DIM; i++)
        acc = fmaf(hs[g][i], w[(size_t)i * OUT_DIM], acc);

    atomicAdd(&g_agg[(size_t)dst[e] * OUT_DIM + o], acc);
}

// ---------------------------------------------------------------------------
// Kernel 6: h = relu(agg + bias); last step writes d_out instead of g_h
// ---------------------------------------------------------------------------
__global__ void k_relu(const float* __restrict__ bias, float* __restrict__ dout,
                       int last) {
    int i = blockIdx.x * 256 + threadIdx.x;
    if (i >= V_NODES * OUT_DIM) return;
    float v = fmaxf(g_agg[i] + bias[i & 63], 0.0f);
    if (last) dout[i] = v;
    else      g_h[i]  = v;
}

// ---------------------------------------------------------------------------
// Launch
// ---------------------------------------------------------------------------
extern "C" void kernel_launch(void* const* d_in, const int* in_sizes, int n_in,
                              void* d_out, int out_size) {
    const float* nf   = (const float*)d_in[0];
    const float* ef   = (const float*)d_in[1];
    const int*   src  = (const int*)  d_in[2];
    const int*   dst  = (const int*)  d_in[3];
    const float* Wp   = (const float*)d_in[4];
    const float* bp   = (const float*)d_in[5];
    const float* We1  = (const float*)d_in[6];
    const float* be1  = (const float*)d_in[7];
    const float* We2  = (const float*)d_in[8];
    const float* be2  = (const float*)d_in[9];
    const float* bias = (const float*)d_in[10];
    float* out = (float*)d_out;

    (void)in_sizes; (void)n_in; (void)out_size;

    // node projection
    k_project<<<V_NODES, OUT_DIM>>>(nf, Wp, bp);
    // edge MLP layer 1
    k_edge1<<<E_EDGES, EHID>>>(ef, We1, be1);
    // edge MLP layer 2 (the big GEMM) -> g_ew
    dim3 gemm_grid(N_EW / 128, (E_EDGES + 127) / 128);   // (32, 782)
    k_gemm<<<gemm_grid, 256>>>(We2, be2);

    // message passing loop
    int nelem_blocks = (V_NODES * OUT_DIM + 255) / 256;  // 6250
    for (int t = 0; t < NSTEPS; t++) {
        k_zero<<<nelem_blocks, 256>>>();
        k_msg<<<E_EDGES / 4, 256>>>(src, dst);
        k_relu<<<nelem_blocks, 256>>>(bias, out, t == NSTEPS - 1 ? 1 : 0);
    }
}

// round 4
// speedup vs baseline: 2.5189x; 2.5189x over previous
#include <cuda_runtime.h>
#include <cuda_bf16.h>
#include <cuda_fp16.h>
#include <cstdint>
#include <cstddef>

// Problem constants
#define V_NODES   25000
#define E_EDGES   100000
#define NODE_IN   74
#define EDGE_IN   12
#define OUT_DIM   64
#define EHID      128
#define NSTEPS    6
#define N_EW      4096        // OUT*OUT

// ---------------------------------------------------------------------------
// Scratch (__device__ globals -- the sanctioned scratch mechanism)
// ---------------------------------------------------------------------------
__device__ float  g_h  [V_NODES * OUT_DIM];                 // 6.4 MB
__device__ float  g_agg[V_NODES * OUT_DIM];                 // 6.4 MB
__device__ __align__(256) __half g_zh [E_EDGES * EHID];     // 25.6 MB  z (fp16)
__device__ __align__(256) __half g_Wt [N_EW * EHID];        // 1 MB     We2^T (fp16)
__device__ __align__(256) __half g_ewh[(size_t)E_EDGES * N_EW]; // 819 MB ew (fp16)

__device__ __forceinline__ uint32_t smem_to_u32(const void* p) {
    uint32_t a;
    asm("{ .reg .u64 t; cvta.to.shared.u64 t, %1; cvt.u32.u64 %0, t; }" : "=r"(a) : "l"(p));
    return a;
}

// ---------------------------------------------------------------------------
// Kernel 1: h = relu(node_feats @ Wp + bp)      [25000 x 74] @ [74 x 64]
// ---------------------------------------------------------------------------
__global__ void k_project(const float* __restrict__ nf,
                          const float* __restrict__ Wp,
                          const float* __restrict__ bp) {
    int v = blockIdx.x;
    int o = threadIdx.x;                 // 64 threads
    __shared__ float s[NODE_IN];
    for (int i = o; i < NODE_IN; i += OUT_DIM) s[i] = nf[v * NODE_IN + i];
    __syncthreads();
    float acc = bp[o];
    #pragma unroll
    for (int i = 0; i < NODE_IN; i++) acc = fmaf(s[i], Wp[i * OUT_DIM + o], acc);
    g_h[v * OUT_DIM + o] = fmaxf(acc, 0.0f);
}

// ---------------------------------------------------------------------------
// Kernel 2: z = relu(edge_feats @ We1 + be1) -> fp16    [100000 x 12] @ [12 x 128]
// ---------------------------------------------------------------------------
__global__ void k_edge1(const float* __restrict__ ef,
                        const float* __restrict__ We1,
                        const float* __restrict__ be1) {
    int e = blockIdx.x;
    int k = threadIdx.x;                 // 128 threads
    __shared__ float s[EDGE_IN];
    if (k < EDGE_IN) s[k] = ef[e * EDGE_IN + k];
    __syncthreads();
    float acc = be1[k];
    #pragma unroll
    for (int j = 0; j < EDGE_IN; j++) acc = fmaf(s[j], We1[j * EHID + k], acc);
    g_zh[e * EHID + k] = __float2half_rn(fmaxf(acc, 0.0f));
}

// ---------------------------------------------------------------------------
// Kernel 2b: Wt[n][k] = (half)We2[k][n]   (tiny one-time transpose, 1 MB out)
// ---------------------------------------------------------------------------
__global__ void k_transpose(const float* __restrict__ We2) {
    int n = blockIdx.x;                  // 4096
    int k = threadIdx.x;                 // 128
    g_Wt[n * EHID + k] = __float2half_rn(We2[(size_t)k * N_EW + n]);
}

// ---------------------------------------------------------------------------
// Kernel 3: HMMA fp16 GEMM  ew = z @ We2 + be2 -> fp16
// mma.sync.m16n8k16.row.col, fp32 accum. CTA tile 128x128, K=128 in one pass.
// 8 warps: 4 (M) x 2 (N), warp tile 32x64.
// Smem rows padded to 136 halves (272 B) -> ldmatrix conflict-free.
// ---------------------------------------------------------------------------
#define AS_STRIDE 136
#define A_OFF     0
#define B_OFF     (128 * AS_STRIDE * 2)          // 34816
#define BIAS_OFF  (2 * 128 * AS_STRIDE * 2)      // 69632
#define GEMM_SMEM (BIAS_OFF + 512 + 128)

__global__ void __launch_bounds__(256)
k_gemm_hmma(const float* __restrict__ be2) {
    extern __shared__ char smem[];
    __half* As = reinterpret_cast<__half*>(smem + A_OFF);
    __half* Bs = reinterpret_cast<__half*>(smem + B_OFF);
    float*  bias_s = reinterpret_cast<float*>(smem + BIAS_OFF);

    const int tid  = threadIdx.x;
    const int wid  = tid >> 5, lane = tid & 31;
    const int warp_m = wid >> 1;                  // 0..3  (32 rows each)
    const int warp_n = wid & 1;                   // 0..1  (64 cols each)
    const int m0 = blockIdx.y * 128;
    const int n0 = blockIdx.x * 128;

    if (tid < 128) bias_s[tid] = be2[n0 + tid];

    // --- load A tile: z rows [m0, m0+128), 128 halves per row ---
    #pragma unroll
    for (int it = 0; it < 8; it++) {
        int idx = tid + 256 * it;                 // 0..2047 uint4 slots
        int r = idx >> 4, c = (idx & 15) * 8;
        int gm = m0 + r;
        uint4 v = make_uint4(0u, 0u, 0u, 0u);
        if (gm < E_EDGES)
            v = *reinterpret_cast<const uint4*>(g_zh + (size_t)gm * EHID + c);
        *reinterpret_cast<uint4*>(As + r * AS_STRIDE + c) = v;
    }
    // --- load B tile: Wt rows [n0, n0+128) (= We2 columns) ---
    #pragma unroll
    for (int it = 0; it < 8; it++) {
        int idx = tid + 256 * it;
        int r = idx >> 4, c = (idx & 15) * 8;
        uint4 v = *reinterpret_cast<const uint4*>(g_Wt + (size_t)(n0 + r) * EHID + c);
        *reinterpret_cast<uint4*>(Bs + r * AS_STRIDE + c) = v;
    }
    __syncthreads();

    uint32_t sbA = smem_to_u32(As);
    uint32_t sbB = smem_to_u32(Bs);

    float acc[2][8][4];
    #pragma unroll
    for (int i = 0; i < 2; i++)
        #pragma unroll
        for (int j = 0; j < 8; j++)
            #pragma unroll
            for (int q = 0; q < 4; q++) acc[i][j][q] = 0.0f;

    const int ar = lane & 15, ac = (lane >> 4) * 8;        // A ldmatrix addr parts
    const int br = lane & 7,  bc = ((lane >> 3) & 1) * 8;  // B ldmatrix addr parts

    #pragma unroll
    for (int ks = 0; ks < 8; ks++) {
        int k0 = ks * 16;
        uint32_t a[2][4];
        #pragma unroll
        for (int msub = 0; msub < 2; msub++) {
            uint32_t addr = sbA + ((warp_m * 32 + msub * 16 + ar) * AS_STRIDE + k0 + ac) * 2;
            asm volatile("ldmatrix.sync.aligned.m8n8.x4.shared.b16 {%0,%1,%2,%3}, [%4];"
                : "=r"(a[msub][0]), "=r"(a[msub][1]), "=r"(a[msub][2]), "=r"(a[msub][3])
                : "r"(addr));
        }
        uint32_t b[8][2];
        #pragma unroll
        for (int nsub = 0; nsub < 8; nsub++) {
            uint32_t addr = sbB + ((warp_n * 64 + nsub * 8 + br) * AS_STRIDE + k0 + bc) * 2;
            asm volatile("ldmatrix.sync.aligned.m8n8.x2.shared.b16 {%0,%1}, [%2];"
                : "=r"(b[nsub][0]), "=r"(b[nsub][1]) : "r"(addr));
        }
        #pragma unroll
        for (int msub = 0; msub < 2; msub++)
            #pragma unroll
            for (int nsub = 0; nsub < 8; nsub++) {
                asm volatile(
                    "mma.sync.aligned.m16n8k16.row.col.f32.f16.f16.f32 "
                    "{%0,%1,%2,%3}, {%4,%5,%6,%7}, {%8,%9}, {%0,%1,%2,%3};"
                    : "+f"(acc[msub][nsub][0]), "+f"(acc[msub][nsub][1]),
                      "+f"(acc[msub][nsub][2]), "+f"(acc[msub][nsub][3])
                    : "r"(a[msub][0]), "r"(a[msub][1]), "r"(a[msub][2]), "r"(a[msub][3]),
                      "r"(b[nsub][0]), "r"(b[nsub][1]));
            }
    }

    // --- epilogue: +bias, convert to fp16, store ---
    const int qrow = lane >> 2;            // 0..7
    const int qcol = (lane & 3) * 2;       // 0,2,4,6
    #pragma unroll
    for (int msub = 0; msub < 2; msub++) {
        int r0 = m0 + warp_m * 32 + msub * 16 + qrow;
        #pragma unroll
        for (int nsub = 0; nsub < 8; nsub++) {
            int lc = warp_n * 64 + nsub * 8 + qcol;        // local col 0..127
            float bx = bias_s[lc], by = bias_s[lc + 1];
            if (r0 < E_EDGES) {
                __half2 h = __floats2half2_rn(acc[msub][nsub][0] + bx,
                                              acc[msub][nsub][1] + by);
                *reinterpret_cast<__half2*>(g_ewh + (size_t)r0 * N_EW + n0 + lc) = h;
            }
            if (r0 + 8 < E_EDGES) {
                __half2 h = __floats2half2_rn(acc[msub][nsub][2] + bx,
                                              acc[msub][nsub][3] + by);
                *reinterpret_cast<__half2*>(g_ewh + (size_t)(r0 + 8) * N_EW + n0 + lc) = h;
            }
        }
    }
}

// ---------------------------------------------------------------------------
// Kernel 4: zero the aggregation buffer
// ---------------------------------------------------------------------------
__global__ void k_zero() {
    int i = blockIdx.x * 256 + threadIdx.x;
    if (i < V_NODES * OUT_DIM) g_agg[i] = 0.0f;
}

// ---------------------------------------------------------------------------
// Kernel 5: msg[e] = h[src[e]] @ ew[e] (fp16 weights), atomic scatter to dst.
// One warp per edge; streams 819 MB of fp16 ew -> HBM-bound.
// ---------------------------------------------------------------------------
__global__ void __launch_bounds__(256)
k_msg(const int* __restrict__ src, const int* __restrict__ dst) {
    int g = threadIdx.x >> 5;                 // warp slot (edge) 0..7
    int o = threadIdx.x & 31;                 // half2 column index
    int e = blockIdx.x * 8 + g;
    __shared__ float hs[8][OUT_DIM];

    int s = src[e];
    hs[g][o]      = g_h[s * OUT_DIM + o];
    hs[g][o + 32] = g_h[s * OUT_DIM + o + 32];
    __syncwarp();

    const __half2* w = reinterpret_cast<const __half2*>(g_ewh + (size_t)e * N_EW) + o;
    float2 acc = make_float2(0.0f, 0.0f);
    #pragma unroll
    for (int i = 0; i < OUT_DIM; i++) {
        float2 wv = __half22float2(w[i * 32]);
        float  hv = hs[g][i];
        acc.x = fmaf(hv, wv.x, acc.x);
        acc.y = fmaf(hv, wv.y, acc.y);
    }
    float* a = &g_agg[(size_t)dst[e] * OUT_DIM + 2 * o];
    atomicAdd(a,     acc.x);
    atomicAdd(a + 1, acc.y);
}

// ---------------------------------------------------------------------------
// Kernel 6: h = relu(agg + bias); last step writes d_out
// ---------------------------------------------------------------------------
__global__ void k_relu(const float* __restrict__ bias, float* __restrict__ dout,
                       int last) {
    int i = blockIdx.x * 256 + threadIdx.x;
    if (i >= V_NODES * OUT_DIM) return;
    float v = fmaxf(g_agg[i] + bias[i & 63], 0.0f);
    if (last) dout[i] = v;
    else      g_h[i]  = v;
}

// ---------------------------------------------------------------------------
// Launch
// ---------------------------------------------------------------------------
extern "C" void kernel_launch(void* const* d_in, const int* in_sizes, int n_in,
                              void* d_out, int out_size) {
    const float* nf   = (const float*)d_in[0];
    const float* ef   = (const float*)d_in[1];
    const int*   src  = (const int*)  d_in[2];
    const int*   dst  = (const int*)  d_in[3];
    const float* Wp   = (const float*)d_in[4];
    const float* bp   = (const float*)d_in[5];
    const float* We1  = (const float*)d_in[6];
    const float* be1  = (const float*)d_in[7];
    const float* We2  = (const float*)d_in[8];
    const float* be2  = (const float*)d_in[9];
    const float* bias = (const float*)d_in[10];
    float* out = (float*)d_out;

    (void)in_sizes; (void)n_in; (void)out_size;

    cudaFuncSetAttribute(k_gemm_hmma, cudaFuncAttributeMaxDynamicSharedMemorySize,
                         GEMM_SMEM);

    k_project<<<V_NODES, OUT_DIM>>>(nf, Wp, bp);
    k_edge1<<<E_EDGES, EHID>>>(ef, We1, be1);
    k_transpose<<<N_EW, EHID>>>(We2);

    dim3 gemm_grid(N_EW / 128, (E_EDGES + 127) / 128);   // (32, 782)
    k_gemm_hmma<<<gemm_grid, 256, GEMM_SMEM>>>(be2);

    int nelem_blocks = (V_NODES * OUT_DIM + 255) / 256;  // 6250
    for (int t = 0; t < NSTEPS; t++) {
        k_zero<<<nelem_blocks, 256>>>();
        k_msg<<<E_EDGES / 8, 256>>>(src, dst);
        k_relu<<<nelem_blocks, 256>>>(bias, out, t == NSTEPS - 1 ? 1 : 0);
    }
}